// round 12
// baseline (speedup 1.0000x reference)
#include <cuda_runtime.h>

#define SEQ   512
#define BATCH 4096
#define HID   30
#define ROWF  40   // floats per (buf,batch) row: 32 loaded (30 h + 2 pad) + 8
#define PF    2    // X prefetch depth per chain (2 x ~400cyc step-pairs cover DRAM latency)

typedef unsigned long long ull;

__device__ __forceinline__ ull pk2(float a, float b) {
    ull r; asm("mov.b64 %0,{%1,%2};" : "=l"(r) : "f"(a), "f"(b)); return r;
}
__device__ __forceinline__ void unpk2(ull v, float& a, float& b) {
    asm("mov.b64 {%0,%1},%2;" : "=f"(a), "=f"(b) : "l"(v));
}
// Packed dual-fp32 FMA / ADD (Blackwell f32x2).
__device__ __forceinline__ ull ffma2(ull a, ull b, ull c) {
    ull d; asm("fma.rn.f32x2 %0,%1,%2,%3;" : "=l"(d) : "l"(a), "l"(b), "l"(c)); return d;
}
__device__ __forceinline__ ull add2(ull a, ull b) {
    ull d; asm("add.rn.f32x2 %0,%1,%2;" : "=l"(d) : "l"(a), "l"(b)); return d;
}

// tanh with PRE-SCALED input (2*log2e folded into weights): tanh = 1 - 2/(exp2(v)+1).
__device__ __forceinline__ float tanh_ps(float v) {
    float e, r;
    asm("ex2.approx.f32 %0, %1;" : "=f"(e) : "f"(v));
    asm("rcp.approx.f32 %0, %1;" : "=f"(r) : "f"(e + 1.0f));
    return fmaf(-2.0f, r, 1.0f);
}

__global__ void __launch_bounds__(32)
rnn_kernel(const float* __restrict__ X,     const float* __restrict__ W_ih,
           const float* __restrict__ W_hh,  const float* __restrict__ b_ih,
           const float* __restrict__ b_hh,  const float* __restrict__ W_out,
           const float* __restrict__ b_out, float* __restrict__ Y)
{
    // h double buffer: hbuf[buf][chain*2+b][k]; chains A (0,1) and B (2,3). pad k>=30 stays 0.
    __shared__ __align__(16) float hbuf[2][4][ROWF];

    const int lane = threadIdx.x;
    const int jp   = lane & 15;            // row-pair index; jp==15 -> y-row (j0) + zero pad (j1)
    const int b    = lane >> 4;            // SIMT batch half
    const int j0   = 2 * jp, j1 = j0 + 1;
    const bool yrow = (jp == 15);
    const int batchA = blockIdx.x * 4 + b;       // chain A
    const int batchB = blockIdx.x * 4 + 2 + b;   // chain B

    const float SC = 2.8853900817779268f;  // 2*log2(e), folded into pre-tanh weights

    // ---- weights packed over (k even, k odd): wa = row j0, wb = row j1 (shared by chains) ----
    ull wa[16], wb[16];
#pragma unroll
    for (int i = 0; i < 16; i++) {
        const int k0 = 2 * i, k1 = 2 * i + 1;
        float a0, a1;
        if (!yrow) {
            a0 = (k0 < HID) ? SC * W_hh[j0 * HID + k0] : 0.0f;
            a1 = (k1 < HID) ? SC * W_hh[j0 * HID + k1] : 0.0f;
        } else {
            a0 = (k0 < HID) ? W_out[k0] : 0.0f;
            a1 = (k1 < HID) ? W_out[k1] : 0.0f;
        }
        float c0 = (!yrow && k0 < HID) ? SC * W_hh[j1 * HID + k0] : 0.0f;
        float c1 = (!yrow && k1 < HID) ? SC * W_hh[j1 * HID + k1] : 0.0f;
        wa[i] = pk2(a0, a1);
        wb[i] = pk2(c0, c1);
    }
    const float wih0 = !yrow ? SC * W_ih[j0] : 0.0f;
    const float wih1 = !yrow ? SC * W_ih[j1] : 0.0f;
    const float bi0  = !yrow ? SC * (b_ih[j0] + b_hh[j0]) : b_out[0];
    const float bi1  = !yrow ? SC * (b_ih[j1] + b_hh[j1]) : 0.0f;

    // ---- zero both buffers incl. pad ----
#pragma unroll
    for (int i = lane; i < 2 * 4 * ROWF; i += 32)
        (&hbuf[0][0][0])[i] = 0.0f;
    __syncwarp();

    const float* XA = X + batchA;  const float* XB = X + batchB;
    float*       YA = Y + batchA;  float*       YB = Y + batchB;

    // ---- X prefetch rings, one per chain ----
    float xbA[PF], xbB[PF];
#pragma unroll
    for (int i = 0; i < PF; i++) { xbA[i] = XA[i * BATCH]; xbB[i] = XB[i * BATCH]; }

    for (int s0 = 0; s0 < SEQ; s0 += PF) {
#pragma unroll
        for (int u = 0; u < PF; u++) {
            const int s = s0 + u;
            const float4* hcA = (const float4*)&hbuf[s & 1][b][0];
            float*        hnA = &hbuf[(s & 1) ^ 1][b][0];
            const float4* hcB = (const float4*)&hbuf[s & 1][2 + b][0];
            float*        hnB = &hbuf[(s & 1) ^ 1][2 + b][0];

            const float xcA = xbA[u];
            const float xcB = xbB[u];
            if (s + PF < SEQ) {
                xbA[u] = XA[(s + PF) * BATCH];
                xbB[u] = XB[(s + PF) * BATCH];
            }

            // ---- two independent matvecs, interleaved for ILP ----
            ull aA0 = pk2(fmaf(wih0, xcA, bi0), 0.0f), aA1 = 0ull;
            ull cA0 = pk2(fmaf(wih1, xcA, bi1), 0.0f), cA1 = 0ull;
            ull aB0 = pk2(fmaf(wih0, xcB, bi0), 0.0f), aB1 = 0ull;
            ull cB0 = pk2(fmaf(wih1, xcB, bi1), 0.0f), cB1 = 0ull;
#pragma unroll
            for (int i = 0; i < 8; i++) {
                const float4 fa = hcA[i];
                const float4 fb = hcB[i];
                const ull hA0 = pk2(fa.x, fa.y), hA1 = pk2(fa.z, fa.w);
                const ull hB0 = pk2(fb.x, fb.y), hB1 = pk2(fb.z, fb.w);
                aA0 = ffma2(wa[2 * i],     hA0, aA0);
                aB0 = ffma2(wa[2 * i],     hB0, aB0);
                aA1 = ffma2(wa[2 * i + 1], hA1, aA1);
                aB1 = ffma2(wa[2 * i + 1], hB1, aB1);
                cA0 = ffma2(wb[2 * i],     hA0, cA0);
                cB0 = ffma2(wb[2 * i],     hB0, cB0);
                cA1 = ffma2(wb[2 * i + 1], hA1, cA1);
                cB1 = ffma2(wb[2 * i + 1], hB1, cB1);
            }
            const ull sA = add2(aA0, aA1), tA = add2(cA0, cA1);
            const ull sB = add2(aB0, aB1), tB = add2(cB0, cB1);
            float sA0, sA1, tA0, tA1, sB0, sB1, tB0, tB1;
            unpk2(sA, sA0, sA1);  unpk2(tA, tA0, tA1);
            unpk2(sB, sB0, sB1);  unpk2(tB, tB0, tB1);
            const float vA0 = sA0 + sA1, vA1 = tA0 + tA1;   // jp==15: vA0 = y_A[s-1]
            const float vB0 = sB0 + sB1, vB1 = tB0 + tB1;

            // ---- y stores (lanes 15/31, predicated) ----
            if (yrow && s > 0) {
                YA[(s - 1) * BATCH] = vA0;
                YB[(s - 1) * BATCH] = vB0;
            }

            // ---- tanh + publish ----
            const float hA0v = tanh_ps(vA0), hA1v = tanh_ps(vA1);
            const float hB0v = tanh_ps(vB0), hB1v = tanh_ps(vB1);
            *(float2*)&hnA[j0] = make_float2(yrow ? 0.0f : hA0v, hA1v);
            *(float2*)&hnB[j0] = make_float2(yrow ? 0.0f : hB0v, hB1v);

            // compiler barrier: keep next step's LDS after these STS (same-warp MIO in-order)
            asm volatile("" ::: "memory");
        }
    }

    // ---- epilogue: y[SEQ-1] for both chains from final state (buffer 0, SEQ even) ----
#pragma unroll
    for (int ch = 0; ch < 2; ch++) {
        const float4* hc = (const float4*)&hbuf[0][2 * ch + b][0];
        ull a0 = pk2(bi0, 0.0f), a1 = 0ull;
#pragma unroll
        for (int i = 0; i < 8; i++) {
            const float4 f = hc[i];
            a0 = ffma2(wa[2 * i],     pk2(f.x, f.y), a0);
            a1 = ffma2(wa[2 * i + 1], pk2(f.z, f.w), a1);
        }
        const ull sa = add2(a0, a1);
        float s0v, s1v;
        unpk2(sa, s0v, s1v);
        if (yrow) {
            float* Yp = ch ? YB : YA;
            Yp[(SEQ - 1) * BATCH] = s0v + s1v;
        }
    }
}

extern "C" void kernel_launch(void* const* d_in, const int* in_sizes, int n_in,
                              void* d_out, int out_size)
{
    (void)in_sizes; (void)n_in; (void)out_size;
    rnn_kernel<<<BATCH / 4, 32>>>(
        (const float*)d_in[0],  // X
        (const float*)d_in[1],  // W_ih
        (const float*)d_in[2],  // W_hh
        (const float*)d_in[3],  // b_ih
        (const float*)d_in[4],  // b_hh
        (const float*)d_in[5],  // W_out
        (const float*)d_in[6],  // b_out
        (float*)d_out);
}

// round 13
// speedup vs baseline: 1.2823x; 1.2823x over previous
#include <cuda_runtime.h>

#define SEQ   512
#define BATCH 4096
#define HID   30
#define ROWP  24   // ull pairs per (buf,b) row: 16 loaded (15 h-pairs + 1 zero pad) + 8 pad
#define PF    4    // X prefetch depth

typedef unsigned long long ull;

__device__ __forceinline__ ull pk2(float a, float b) {
    ull r; asm("mov.b64 %0,{%1,%2};" : "=l"(r) : "f"(a), "f"(b)); return r;
}
__device__ __forceinline__ void unpk2(ull v, float& a, float& b) {
    asm("mov.b64 {%0,%1},%2;" : "=f"(a), "=f"(b) : "l"(v));
}
// Packed dual-fp32 FMA / ADD (Blackwell f32x2).
__device__ __forceinline__ ull ffma2(ull a, ull b, ull c) {
    ull d; asm("fma.rn.f32x2 %0,%1,%2,%3;" : "=l"(d) : "l"(a), "l"(b), "l"(c)); return d;
}
__device__ __forceinline__ ull add2(ull a, ull b) {
    ull d; asm("add.rn.f32x2 %0,%1,%2;" : "=l"(d) : "l"(a), "l"(b)); return d;
}
// Single-op hardware tanh (MUFU.TANH): 1 instr, 16-cyc lat vs ~40 for ex2/rcp chain.
// Abs err ~1e-4; tanh(0) == 0 exactly.
__device__ __forceinline__ float tanhap(float v) {
    float r; asm("tanh.approx.f32 %0, %1;" : "=f"(r) : "f"(v));
    return r;
}

__global__ void __launch_bounds__(32)
rnn_kernel(const float* __restrict__ X,     const float* __restrict__ W_ih,
           const float* __restrict__ W_hh,  const float* __restrict__ b_ih,
           const float* __restrict__ b_hh,  const float* __restrict__ W_out,
           const float* __restrict__ b_out, float* __restrict__ Y)
{
    // h double buffer, PACKED pairs: hbuf[buf][b][p] = (h[2p], h[2p+1]); p=15 zero pad.
    __shared__ __align__(16) ull hbuf[2][2][ROWP];

    const int lane = threadIdx.x;
    const int jp   = lane & 15;            // row-pair index; jp==15 -> y-row (j0) + zero pad (j1)
    const int b    = lane >> 4;            // SIMT batch half
    const int j0   = 2 * jp, j1 = j0 + 1;
    const bool yrow = (jp == 15);
    const int batch = blockIdx.x * 2 + b;

    // ---- weights packed over (k even, k odd): wa = row j0, wb = row j1 ----
    // jp<15: W_hh rows (PLAIN, no prescale — tanh.approx takes the raw argument);
    // jp==15: wa = W_out, wb = 0 (free output projection).
    ull wa[16], wb[16];
#pragma unroll
    for (int i = 0; i < 16; i++) {
        const int k0 = 2 * i, k1 = 2 * i + 1;
        float a0, a1;
        if (!yrow) {
            a0 = (k0 < HID) ? W_hh[j0 * HID + k0] : 0.0f;
            a1 = (k1 < HID) ? W_hh[j0 * HID + k1] : 0.0f;
        } else {
            a0 = (k0 < HID) ? W_out[k0] : 0.0f;
            a1 = (k1 < HID) ? W_out[k1] : 0.0f;
        }
        float c0 = (!yrow && k0 < HID) ? W_hh[j1 * HID + k0] : 0.0f;
        float c1 = (!yrow && k1 < HID) ? W_hh[j1 * HID + k1] : 0.0f;
        wa[i] = pk2(a0, a1);
        wb[i] = pk2(c0, c1);
    }
    const float wih0 = !yrow ? W_ih[j0] : 0.0f;
    const float wih1 = !yrow ? W_ih[j1] : 0.0f;
    const float bi0  = !yrow ? (b_ih[j0] + b_hh[j0]) : b_out[0];
    const float bi1  = !yrow ? (b_ih[j1] + b_hh[j1]) : 0.0f;

    // ---- zero both buffers incl. pad ----
#pragma unroll
    for (int i = lane; i < 2 * 2 * ROWP; i += 32)
        (&hbuf[0][0][0])[i] = 0ull;
    __syncwarp();

    const float* Xb = X + batch;
    float*       Yb = Y + batch;

    // ---- X prefetch ring ----
    float xbuf[PF];
#pragma unroll
    for (int i = 0; i < PF; i++) xbuf[i] = Xb[i * BATCH];

    for (int s0 = 0; s0 < SEQ; s0 += PF) {
        const float* Xpf = Xb + (s0 + PF) * BATCH;
        const bool more = (s0 + PF) < SEQ;

#pragma unroll
        for (int u = 0; u < PF; u++) {
            const int s = s0 + u;
            // static ping-pong: s&1 == u&1 (PF even, s0 multiple of PF)
            const ulonglong2* hc = (const ulonglong2*)&hbuf[u & 1][b][0];
            ull*              hn = &hbuf[(u & 1) ^ 1][b][0];

            const float xc = xbuf[u];
            if (more) xbuf[u] = Xpf[u * BATCH];

            // ---- matvec rows j0,j1: 16 k-pairs, 8 split chains (depth 4), 8 LDS.128 ----
            const ulonglong2 g0 = hc[0], g1 = hc[1], g2 = hc[2], g3 = hc[3];
            const ulonglong2 g4 = hc[4], g5 = hc[5], g6 = hc[6], g7 = hc[7];
            ull a0 = pk2(fmaf(wih0, xc, bi0), 0.0f), a1 = 0ull, a2 = 0ull, a3 = 0ull;
            ull c0 = pk2(fmaf(wih1, xc, bi1), 0.0f), c1 = 0ull, c2 = 0ull, c3 = 0ull;
            a0 = ffma2(wa[0],  g0.x, a0);  c0 = ffma2(wb[0],  g0.x, c0);
            a1 = ffma2(wa[1],  g0.y, a1);  c1 = ffma2(wb[1],  g0.y, c1);
            a2 = ffma2(wa[2],  g1.x, a2);  c2 = ffma2(wb[2],  g1.x, c2);
            a3 = ffma2(wa[3],  g1.y, a3);  c3 = ffma2(wb[3],  g1.y, c3);
            a0 = ffma2(wa[4],  g2.x, a0);  c0 = ffma2(wb[4],  g2.x, c0);
            a1 = ffma2(wa[5],  g2.y, a1);  c1 = ffma2(wb[5],  g2.y, c1);
            a2 = ffma2(wa[6],  g3.x, a2);  c2 = ffma2(wb[6],  g3.x, c2);
            a3 = ffma2(wa[7],  g3.y, a3);  c3 = ffma2(wb[7],  g3.y, c3);
            a0 = ffma2(wa[8],  g4.x, a0);  c0 = ffma2(wb[8],  g4.x, c0);
            a1 = ffma2(wa[9],  g4.y, a1);  c1 = ffma2(wb[9],  g4.y, c1);
            a2 = ffma2(wa[10], g5.x, a2);  c2 = ffma2(wb[10], g5.x, c2);
            a3 = ffma2(wa[11], g5.y, a3);  c3 = ffma2(wb[11], g5.y, c3);
            a0 = ffma2(wa[12], g6.x, a0);  c0 = ffma2(wb[12], g6.x, c0);
            a1 = ffma2(wa[13], g6.y, a1);  c1 = ffma2(wb[13], g6.y, c1);
            a2 = ffma2(wa[14], g7.x, a2);  c2 = ffma2(wb[14], g7.x, c2);
            a3 = ffma2(wa[15], g7.y, a3);  c3 = ffma2(wb[15], g7.y, c3);

            const ull sa = add2(add2(a0, a1), add2(a2, a3));
            const ull sc = add2(add2(c0, c1), add2(c2, c3));
            float sa0, sa1, sc0, sc1;
            unpk2(sa, sa0, sa1);
            unpk2(sc, sc0, sc1);
            const float v0 = sa0 + sa1;    // jp<15: pre-tanh j0 ; jp==15: y[s-1]
            const float v1 = sc0 + sc1;

            // ---- y store (lanes 15/31, predicated — warp stays convergent) ----
            if (yrow && s > 0) Yb[(s - 1) * BATCH] = v0;

            // ---- tanh (1 MUFU op) + publish packed pair (STS.64) ----
            const float h0 = tanhap(v0);
            const float h1 = tanhap(v1);   // jp==15: v1==0 -> h1==0 exactly
            hn[jp] = pk2(yrow ? 0.0f : h0, h1);

            // compiler barrier: keep next step's LDS after this STS (same-warp MIO in-order)
            asm volatile("" ::: "memory");
        }
    }

    // ---- epilogue: y[SEQ-1] from final state (buffer 0, SEQ even) ----
    {
        const ulonglong2* hc = (const ulonglong2*)&hbuf[0][b][0];
        ull a0 = pk2(bi0, 0.0f), a1 = 0ull;
#pragma unroll
        for (int i = 0; i < 8; i++) {
            const ulonglong2 g = hc[i];
            a0 = ffma2(wa[2 * i],     g.x, a0);
            a1 = ffma2(wa[2 * i + 1], g.y, a1);
        }
        const ull sa = add2(a0, a1);
        float s0v, s1v;
        unpk2(sa, s0v, s1v);
        if (yrow) Yb[(SEQ - 1) * BATCH] = s0v + s1v;
    }
}

extern "C" void kernel_launch(void* const* d_in, const int* in_sizes, int n_in,
                              void* d_out, int out_size)
{
    (void)in_sizes; (void)n_in; (void)out_size;
    rnn_kernel<<<BATCH / 2, 32>>>(
        (const float*)d_in[0],  // X
        (const float*)d_in[1],  // W_ih
        (const float*)d_in[2],  // W_hh
        (const float*)d_in[3],  // b_ih
        (const float*)d_in[4],  // b_hh
        (const float*)d_in[5],  // W_out
        (const float*)d_in[6],  // b_out
        (float*)d_out);
}